// round 2
// baseline (speedup 1.0000x reference)
#include <cuda_runtime.h>

#define D_MODEL   768
#define NUM_HEADS 12
#define DQK       64
#define SEQ       2048
#define BATCH     2
#define NROWS     (BATCH*SEQ)          // 4096
#define NEG_INF_F (-1000000000.0f)

// Scratch (device globals: allocation-free per harness rules)
__device__ float g_q[BATCH*NUM_HEADS*SEQ*DQK];     // [B,H,S,d]
__device__ float g_k[BATCH*NUM_HEADS*SEQ*DQK];
__device__ float g_v[BATCH*NUM_HEADS*SEQ*DQK];
__device__ float g_attn[NROWS*D_MODEL];            // [B,S,H*d]

// ---------------------------------------------------------------------------
// Fused Q/K/V projection: Y = X @ W^T + bias, head-split into g_q/g_k/g_v.
// blockIdx.z selects which of the three projections this block computes.
// Block: 64x64 output tile, 256 threads, 4x4 per thread, BK=16.
// ---------------------------------------------------------------------------
__global__ __launch_bounds__(256) void qkv_kernel(
    const float* __restrict__ Qin, const float* __restrict__ Wq, const float* __restrict__ bq,
    const float* __restrict__ Kin, const float* __restrict__ Wk, const float* __restrict__ bk,
    const float* __restrict__ Vin, const float* __restrict__ Wv, const float* __restrict__ bv)
{
    __shared__ float Xs[16][68];   // [k][n]
    __shared__ float Ws[16][68];   // [k][o]

    const int z = blockIdx.z;
    const float* X    = (z == 0) ? Qin : (z == 1) ? Kin : Vin;
    const float* W    = (z == 0) ? Wq  : (z == 1) ? Wk  : Wv;
    const float* bias = (z == 0) ? bq  : (z == 1) ? bk  : bv;
    float* dst        = (z == 0) ? g_q : (z == 1) ? g_k : g_v;

    const int tid = threadIdx.x;
    const int tx  = tid & 15;          // output col group
    const int ty  = tid >> 4;          // output row group
    const int n0  = blockIdx.y * 64;
    const int o0  = blockIdx.x * 64;

    const int lrow = tid >> 2;         // 0..63
    const int kg   = (tid & 3) * 4;    // 0,4,8,12
    const float* Xp = X + (size_t)(n0 + lrow) * D_MODEL + kg;
    const float* Wp = W + (size_t)(o0 + lrow) * D_MODEL + kg;

    float acc[4][4];
#pragma unroll
    for (int i = 0; i < 4; i++)
#pragma unroll
        for (int j = 0; j < 4; j++) acc[i][j] = 0.f;

#pragma unroll 4
    for (int k0 = 0; k0 < D_MODEL; k0 += 16) {
        float4 xv = *(const float4*)(Xp + k0);
        float4 wv = *(const float4*)(Wp + k0);
        Xs[kg+0][lrow] = xv.x; Xs[kg+1][lrow] = xv.y;
        Xs[kg+2][lrow] = xv.z; Xs[kg+3][lrow] = xv.w;
        Ws[kg+0][lrow] = wv.x; Ws[kg+1][lrow] = wv.y;
        Ws[kg+2][lrow] = wv.z; Ws[kg+3][lrow] = wv.w;
        __syncthreads();
#pragma unroll
        for (int kk = 0; kk < 16; kk++) {
            float4 a = *(const float4*)&Xs[kk][ty*4];
            float4 b = *(const float4*)&Ws[kk][tx*4];
            float av[4] = {a.x, a.y, a.z, a.w};
            float bv4[4] = {b.x, b.y, b.z, b.w};
#pragma unroll
            for (int i = 0; i < 4; i++)
#pragma unroll
                for (int j = 0; j < 4; j++) acc[i][j] += av[i] * bv4[j];
        }
        __syncthreads();
    }

    float4 bsv = *(const float4*)(bias + o0 + tx*4);
    float bb[4] = {bsv.x, bsv.y, bsv.z, bsv.w};
    const int h = blockIdx.x;          // 64-wide tile == one head
#pragma unroll
    for (int i = 0; i < 4; i++) {
        int n = n0 + ty*4 + i;
        float4 r;
        r.x = acc[i][0] + bb[0]; r.y = acc[i][1] + bb[1];
        r.z = acc[i][2] + bb[2]; r.w = acc[i][3] + bb[3];
        int b = n >> 11;               // n / SEQ
        int s = n & (SEQ - 1);
        *(float4*)&dst[(((size_t)(b*NUM_HEADS + h))*SEQ + s)*DQK + tx*4] = r;
    }
}

// ---------------------------------------------------------------------------
// Output projection: out = g_attn @ Wo^T + bo, flat [4096,768] destination.
// ---------------------------------------------------------------------------
__global__ __launch_bounds__(256) void oproj_kernel(const float* __restrict__ W,
                                                    const float* __restrict__ bias,
                                                    float* __restrict__ dst)
{
    __shared__ float Xs[16][68];
    __shared__ float Ws[16][68];

    const int tid = threadIdx.x;
    const int tx  = tid & 15;
    const int ty  = tid >> 4;
    const int n0  = blockIdx.y * 64;
    const int o0  = blockIdx.x * 64;

    const int lrow = tid >> 2;
    const int kg   = (tid & 3) * 4;
    const float* Xp = g_attn + (size_t)(n0 + lrow) * D_MODEL + kg;
    const float* Wp = W + (size_t)(o0 + lrow) * D_MODEL + kg;

    float acc[4][4];
#pragma unroll
    for (int i = 0; i < 4; i++)
#pragma unroll
        for (int j = 0; j < 4; j++) acc[i][j] = 0.f;

#pragma unroll 4
    for (int k0 = 0; k0 < D_MODEL; k0 += 16) {
        float4 xv = *(const float4*)(Xp + k0);
        float4 wv = *(const float4*)(Wp + k0);
        Xs[kg+0][lrow] = xv.x; Xs[kg+1][lrow] = xv.y;
        Xs[kg+2][lrow] = xv.z; Xs[kg+3][lrow] = xv.w;
        Ws[kg+0][lrow] = wv.x; Ws[kg+1][lrow] = wv.y;
        Ws[kg+2][lrow] = wv.z; Ws[kg+3][lrow] = wv.w;
        __syncthreads();
#pragma unroll
        for (int kk = 0; kk < 16; kk++) {
            float4 a = *(const float4*)&Xs[kk][ty*4];
            float4 b = *(const float4*)&Ws[kk][tx*4];
            float av[4] = {a.x, a.y, a.z, a.w};
            float bv4[4] = {b.x, b.y, b.z, b.w};
#pragma unroll
            for (int i = 0; i < 4; i++)
#pragma unroll
                for (int j = 0; j < 4; j++) acc[i][j] += av[i] * bv4[j];
        }
        __syncthreads();
    }

    float4 bsv = *(const float4*)(bias + o0 + tx*4);
    float bb[4] = {bsv.x, bsv.y, bsv.z, bsv.w};
#pragma unroll
    for (int i = 0; i < 4; i++) {
        int n = n0 + ty*4 + i;
        float4 r;
        r.x = acc[i][0] + bb[0]; r.y = acc[i][1] + bb[1];
        r.z = acc[i][2] + bb[2]; r.w = acc[i][3] + bb[3];
        *(float4*)&dst[(size_t)n * D_MODEL + o0 + tx*4] = r;
    }
}

// ---------------------------------------------------------------------------
// Flash-style causal attention per (b, h, 64-row q tile). 256 threads.
// Also materializes the masked pre-softmax scores (reference output #2).
// Smem: Qs[64][65], Vs[64][64], KP[64][65] (K then reused for P). 49664 B.
// ---------------------------------------------------------------------------
__global__ __launch_bounds__(256) void attn_kernel(float* __restrict__ scores)
{
    extern __shared__ float sm[];
    float* Qs = sm;                    // [64][65]
    float* Vs = sm + 64*65;            // [64][64]
    float* KP = Vs + 64*64;            // [64][65]

    const int tid = threadIdx.x;
    const int tx  = tid & 15;
    const int ty  = tid >> 4;
    const int t   = blockIdx.x;        // q tile 0..31
    const int h   = blockIdx.y;
    const int b   = blockIdx.z;
    const int bh  = b * NUM_HEADS + h;

    const float* qbase = g_q + (size_t)bh * SEQ * DQK;
    const float* kbase = g_k + (size_t)bh * SEQ * DQK;
    const float* vbase = g_v + (size_t)bh * SEQ * DQK;
    float* sc = scores + (size_t)bh * SEQ * SEQ;
    const int r0 = t * 64;

    const int lrow = tid >> 2;         // 0..63
    const int dg   = (tid & 3) * 4;    // 0,4,8,12

    // load Q tile (64x64), stride-65 rows
#pragma unroll
    for (int c = 0; c < 4; c++) {
        int col = dg + c*16;
        float4 qv = *(const float4*)(qbase + (size_t)(r0 + lrow)*DQK + col);
        Qs[lrow*65 + col+0] = qv.x; Qs[lrow*65 + col+1] = qv.y;
        Qs[lrow*65 + col+2] = qv.z; Qs[lrow*65 + col+3] = qv.w;
    }

    float m_i[4], l_i[4], O[4][4];
#pragma unroll
    for (int i = 0; i < 4; i++) {
        m_i[i] = -1e30f; l_i[i] = 0.f;
#pragma unroll
        for (int j = 0; j < 4; j++) O[i][j] = 0.f;
    }

    for (int jt = 0; jt <= t; jt++) {
        // load K (stride-65) and V (natural) tiles
#pragma unroll
        for (int c = 0; c < 4; c++) {
            int col = dg + c*16;
            float4 kv = *(const float4*)(kbase + (size_t)(jt*64 + lrow)*DQK + col);
            KP[lrow*65 + col+0] = kv.x; KP[lrow*65 + col+1] = kv.y;
            KP[lrow*65 + col+2] = kv.z; KP[lrow*65 + col+3] = kv.w;
            float4 vv = *(const float4*)(vbase + (size_t)(jt*64 + lrow)*DQK + col);
            *(float4*)&Vs[lrow*64 + col] = vv;
        }
        __syncthreads();

        // S = Q K^T
        float s4[4][4];
#pragma unroll
        for (int i = 0; i < 4; i++)
#pragma unroll
            for (int j = 0; j < 4; j++) s4[i][j] = 0.f;

#pragma unroll 8
        for (int dd = 0; dd < DQK; dd++) {
            float av[4], bv[4];
#pragma unroll
            for (int i = 0; i < 4; i++) av[i] = Qs[(ty*4+i)*65 + dd];
#pragma unroll
            for (int j = 0; j < 4; j++) bv[j] = KP[(tx*4+j)*65 + dd];
#pragma unroll
            for (int i = 0; i < 4; i++)
#pragma unroll
                for (int j = 0; j < 4; j++) s4[i][j] += av[i] * bv[j];
        }

        // scale, causal mask, write pre-softmax scores
#pragma unroll
        for (int i = 0; i < 4; i++) {
            int qrow = r0 + ty*4 + i;
            float4 w;
            float vv[4];
#pragma unroll
            for (int j = 0; j < 4; j++) {
                int kcol = jt*64 + tx*4 + j;
                float v = s4[i][j] * 0.125f;          // / sqrt(64)
                v = (kcol <= qrow) ? v : NEG_INF_F;
                s4[i][j] = v;
                vv[j] = v;
            }
            w.x = vv[0]; w.y = vv[1]; w.z = vv[2]; w.w = vv[3];
            *(float4*)&sc[(size_t)qrow*SEQ + jt*64 + tx*4] = w;
        }
        __syncthreads();   // everyone done reading KP as K

        // online softmax (row state replicated across the 16 tx lanes)
#pragma unroll
        for (int i = 0; i < 4; i++) {
            float tm = fmaxf(fmaxf(s4[i][0], s4[i][1]), fmaxf(s4[i][2], s4[i][3]));
            tm = fmaxf(tm, __shfl_xor_sync(0xffffffffu, tm, 8));
            tm = fmaxf(tm, __shfl_xor_sync(0xffffffffu, tm, 4));
            tm = fmaxf(tm, __shfl_xor_sync(0xffffffffu, tm, 2));
            tm = fmaxf(tm, __shfl_xor_sync(0xffffffffu, tm, 1));
            float mnew = fmaxf(m_i[i], tm);
            float corr = __expf(m_i[i] - mnew);
            float rs = 0.f;
#pragma unroll
            for (int j = 0; j < 4; j++) {
                float p = __expf(s4[i][j] - mnew);    // masked -1e9 -> 0
                s4[i][j] = p;                          // reuse regs as P
                rs += p;
            }
            rs += __shfl_xor_sync(0xffffffffu, rs, 8);
            rs += __shfl_xor_sync(0xffffffffu, rs, 4);
            rs += __shfl_xor_sync(0xffffffffu, rs, 2);
            rs += __shfl_xor_sync(0xffffffffu, rs, 1);
            l_i[i] = l_i[i] * corr + rs;
            m_i[i] = mnew;
#pragma unroll
            for (int j = 0; j < 4; j++) O[i][j] *= corr;
            // store P into KP region (stride 65)
#pragma unroll
            for (int j = 0; j < 4; j++)
                KP[(ty*4+i)*65 + tx*4 + j] = s4[i][j];
        }
        __syncthreads();

        // O += P @ V
#pragma unroll 4
        for (int kk = 0; kk < 64; kk++) {
            float4 vvv = *(const float4*)&Vs[kk*64 + tx*4];
            float bv[4] = {vvv.x, vvv.y, vvv.z, vvv.w};
#pragma unroll
            for (int i = 0; i < 4; i++) {
                float a = KP[(ty*4+i)*65 + kk];
#pragma unroll
                for (int j = 0; j < 4; j++) O[i][j] += a * bv[j];
            }
        }
        __syncthreads();   // before next tile's loads overwrite KP/Vs
    }

    // normalize and write attn output in [B,S,H*d] layout
#pragma unroll
    for (int i = 0; i < 4; i++) {
        float inv = 1.0f / l_i[i];
        int row = r0 + ty*4 + i;
        float4 r;
        r.x = O[i][0]*inv; r.y = O[i][1]*inv;
        r.z = O[i][2]*inv; r.w = O[i][3]*inv;
        *(float4*)&g_attn[((size_t)(b*SEQ + row))*D_MODEL + h*DQK + tx*4] = r;
    }

    // fill fully-masked score region (cols >= (t+1)*64) with -1e9
    int rem = 31 - t;
    if (rem > 0) {
        int wf4 = rem * 16;            // float4s per row
        int total = 64 * wf4;
        float4 nv = make_float4(NEG_INF_F, NEG_INF_F, NEG_INF_F, NEG_INF_F);
        for (int idx = tid; idx < total; idx += 256) {
            int rr = idx / wf4;
            int cc = idx - rr * wf4;
            *(float4*)&sc[(size_t)(r0 + rr)*SEQ + (t+1)*64 + cc*4] = nv;
        }
    }
}

#define ATTN_SMEM_BYTES ((64*65 + 64*64 + 64*65) * 4)

extern "C" void kernel_launch(void* const* d_in, const int* in_sizes, int n_in,
                              void* d_out, int out_size)
{
    const float* Q  = (const float*)d_in[0];
    const float* K  = (const float*)d_in[1];
    const float* V  = (const float*)d_in[2];
    // d_in[3] = mask (bool causal) — deterministic, not needed
    const float* Wq = (const float*)d_in[4];
    const float* bq = (const float*)d_in[5];
    const float* Wk = (const float*)d_in[6];
    const float* bk = (const float*)d_in[7];
    const float* Wv = (const float*)d_in[8];
    const float* bv = (const float*)d_in[9];
    const float* Wo = (const float*)d_in[10];
    const float* bo = (const float*)d_in[11];

    float* out    = (float*)d_out;                       // [B,S,768]
    float* scores = out + (size_t)NROWS * D_MODEL;       // [B,H,S,S]

    cudaFuncSetAttribute(attn_kernel,
                         cudaFuncAttributeMaxDynamicSharedMemorySize,
                         ATTN_SMEM_BYTES);

    dim3 qkvgrid(D_MODEL / 64, NROWS / 64, 3);   // (12, 64, 3)
    qkv_kernel<<<qkvgrid, 256>>>(Q, Wq, bq, K, Wk, bk, V, Wv, bv);

    dim3 agrid(SEQ / 64, NUM_HEADS, BATCH);      // (32, 12, 2)
    attn_kernel<<<agrid, 256, ATTN_SMEM_BYTES>>>(scores);

    dim3 ogrid(D_MODEL / 64, NROWS / 64);        // (12, 64)
    oproj_kernel<<<ogrid, 256>>>(Wo, bo, out);
}

// round 6
// speedup vs baseline: 1.1410x; 1.1410x over previous
#include <cuda_runtime.h>

#define D_MODEL   768
#define NUM_HEADS 12
#define DQK       64
#define SEQ       2048
#define BATCH     2
#define NROWS     (BATCH*SEQ)          // 4096
#define NEG_INF_F (-1000000000.0f)

// Scratch (device globals: allocation-free per harness rules)
__device__ float g_q[BATCH*NUM_HEADS*SEQ*DQK];     // [B,H,S,d]
__device__ float g_k[BATCH*NUM_HEADS*SEQ*DQK];
__device__ float g_v[BATCH*NUM_HEADS*SEQ*DQK];
__device__ float g_attn[NROWS*D_MODEL];            // [B,S,H*d]

// ---------------- packed fp32x2 helpers (SASS FFMA2 path) -------------------
typedef unsigned long long u64;

__device__ __forceinline__ u64 pk2(float lo, float hi) {
    u64 r;
    asm("mov.b64 %0, {%1, %2};" : "=l"(r) : "f"(lo), "f"(hi));
    return r;
}
__device__ __forceinline__ void upk2(u64 v, float& lo, float& hi) {
    asm("mov.b64 {%0, %1}, %2;" : "=f"(lo), "=f"(hi) : "l"(v));
}
__device__ __forceinline__ void ffma2(u64& d, u64 a, u64 b) {
    asm("fma.rn.f32x2 %0, %1, %2, %0;" : "+l"(d) : "l"(a), "l"(b));
}
__device__ __forceinline__ u64 fmul2(u64 a, u64 b) {
    u64 r;
    asm("mul.rn.f32x2 %0, %1, %2;" : "=l"(r) : "l"(a), "l"(b));
    return r;
}

// ---------------------------------------------------------------------------
// Shared GEMM core: 128x128 output tile, BK=16, 256 threads, 8x8 per thread,
// packed f32x2 accumulators (acc[i][j] holds output cols 2j, 2j+1 of row i).
// ---------------------------------------------------------------------------
#define BM 128
#define BN 128
#define BKP 16
#define LDT 132   // padded smem stride (multiple of 4 for LDS.128 alignment)

__device__ __forceinline__ void gemm_core(const float* __restrict__ X,
                                          const float* __restrict__ W,
                                          int n0, int o0,
                                          float* XsT, float* WsT,
                                          u64 acc[8][4])
{
    const int tid  = threadIdx.x;
    const int tx   = tid & 15;
    const int ty   = tid >> 4;
    const int lrow = tid >> 1;          // 0..127
    const int kg   = (tid & 1) * 8;     // 0 or 8

    const float* Xp = X + (size_t)(n0 + lrow) * D_MODEL + kg;
    const float* Wp = W + (size_t)(o0 + lrow) * D_MODEL + kg;

#pragma unroll
    for (int i = 0; i < 8; i++)
#pragma unroll
        for (int j = 0; j < 4; j++) acc[i][j] = 0ull;

#pragma unroll 1
    for (int k0 = 0; k0 < D_MODEL; k0 += BKP) {
        float4 x0 = *(const float4*)(Xp + k0);
        float4 x1 = *(const float4*)(Xp + k0 + 4);
        float4 w0 = *(const float4*)(Wp + k0);
        float4 w1 = *(const float4*)(Wp + k0 + 4);
        XsT[(kg+0)*LDT + lrow] = x0.x; XsT[(kg+1)*LDT + lrow] = x0.y;
        XsT[(kg+2)*LDT + lrow] = x0.z; XsT[(kg+3)*LDT + lrow] = x0.w;
        XsT[(kg+4)*LDT + lrow] = x1.x; XsT[(kg+5)*LDT + lrow] = x1.y;
        XsT[(kg+6)*LDT + lrow] = x1.z; XsT[(kg+7)*LDT + lrow] = x1.w;
        WsT[(kg+0)*LDT + lrow] = w0.x; WsT[(kg+1)*LDT + lrow] = w0.y;
        WsT[(kg+2)*LDT + lrow] = w0.z; WsT[(kg+3)*LDT + lrow] = w0.w;
        WsT[(kg+4)*LDT + lrow] = w1.x; WsT[(kg+5)*LDT + lrow] = w1.y;
        WsT[(kg+6)*LDT + lrow] = w1.z; WsT[(kg+7)*LDT + lrow] = w1.w;
        __syncthreads();

#pragma unroll
        for (int kk = 0; kk < BKP; kk++) {
            float4 a0 = *(const float4*)&XsT[kk*LDT + ty*8];
            float4 a1 = *(const float4*)&XsT[kk*LDT + ty*8 + 4];
            float4 b0 = *(const float4*)&WsT[kk*LDT + tx*8];
            float4 b1 = *(const float4*)&WsT[kk*LDT + tx*8 + 4];
            u64 bb[4] = { pk2(b0.x,b0.y), pk2(b0.z,b0.w),
                          pk2(b1.x,b1.y), pk2(b1.z,b1.w) };
            float av[8] = { a0.x,a0.y,a0.z,a0.w, a1.x,a1.y,a1.z,a1.w };
#pragma unroll
            for (int i = 0; i < 8; i++) {
                u64 ad = pk2(av[i], av[i]);
#pragma unroll
                for (int j = 0; j < 4; j++) ffma2(acc[i][j], ad, bb[j]);
            }
        }
        __syncthreads();
    }
}

// ---------------------------------------------------------------------------
// Fused Q/K/V projection, head-split output. blockIdx.z picks projection.
// ---------------------------------------------------------------------------
__global__ __launch_bounds__(256) void qkv_kernel(
    const float* __restrict__ Qin, const float* __restrict__ Wq, const float* __restrict__ bq,
    const float* __restrict__ Kin, const float* __restrict__ Wk, const float* __restrict__ bk,
    const float* __restrict__ Vin, const float* __restrict__ Wv, const float* __restrict__ bv)
{
    __shared__ float XsT[BKP*LDT];
    __shared__ float WsT[BKP*LDT];

    const int z = blockIdx.z;
    const float* X    = (z == 0) ? Qin : (z == 1) ? Kin : Vin;
    const float* W    = (z == 0) ? Wq  : (z == 1) ? Wk  : Wv;
    const float* bias = (z == 0) ? bq  : (z == 1) ? bk  : bv;
    float* dst        = (z == 0) ? g_q : (z == 1) ? g_k : g_v;

    const int n0 = blockIdx.y * BM;
    const int o0 = blockIdx.x * BN;
    const int tx = threadIdx.x & 15;
    const int ty = threadIdx.x >> 4;

    u64 acc[8][4];
    gemm_core(X, W, n0, o0, XsT, WsT, acc);

    float bb[8];
    {
        float4 c0 = *(const float4*)(bias + o0 + tx*8);
        float4 c1 = *(const float4*)(bias + o0 + tx*8 + 4);
        bb[0]=c0.x; bb[1]=c0.y; bb[2]=c0.z; bb[3]=c0.w;
        bb[4]=c1.x; bb[5]=c1.y; bb[6]=c1.z; bb[7]=c1.w;
    }
    const int h   = blockIdx.x * 2 + (tx >> 3);   // 128-wide tile = 2 heads
    const int cih = (tx * 8) & 63;                // col within head

#pragma unroll
    for (int i = 0; i < 8; i++) {
        int n = n0 + ty*8 + i;
        int b = n >> 11;               // n / SEQ
        int s = n & (SEQ - 1);
        float o[8];
#pragma unroll
        for (int j = 0; j < 4; j++) upk2(acc[i][j], o[2*j], o[2*j+1]);
#pragma unroll
        for (int j = 0; j < 8; j++) o[j] += bb[j];
        float* dp = dst + (((size_t)(b*NUM_HEADS + h))*SEQ + s)*DQK + cih;
        *(float4*)(dp)     = make_float4(o[0], o[1], o[2], o[3]);
        *(float4*)(dp + 4) = make_float4(o[4], o[5], o[6], o[7]);
    }
}

// ---------------------------------------------------------------------------
// Output projection: out = g_attn @ Wo^T + bo, flat [4096,768].
// ---------------------------------------------------------------------------
__global__ __launch_bounds__(256) void oproj_kernel(const float* __restrict__ W,
                                                    const float* __restrict__ bias,
                                                    float* __restrict__ dst)
{
    __shared__ float XsT[BKP*LDT];
    __shared__ float WsT[BKP*LDT];

    const int n0 = blockIdx.y * BM;
    const int o0 = blockIdx.x * BN;
    const int tx = threadIdx.x & 15;
    const int ty = threadIdx.x >> 4;

    u64 acc[8][4];
    gemm_core(g_attn, W, n0, o0, XsT, WsT, acc);

    float bb[8];
    {
        float4 c0 = *(const float4*)(bias + o0 + tx*8);
        float4 c1 = *(const float4*)(bias + o0 + tx*8 + 4);
        bb[0]=c0.x; bb[1]=c0.y; bb[2]=c0.z; bb[3]=c0.w;
        bb[4]=c1.x; bb[5]=c1.y; bb[6]=c1.z; bb[7]=c1.w;
    }
#pragma unroll
    for (int i = 0; i < 8; i++) {
        int n = n0 + ty*8 + i;
        float o[8];
#pragma unroll
        for (int j = 0; j < 4; j++) upk2(acc[i][j], o[2*j], o[2*j+1]);
#pragma unroll
        for (int j = 0; j < 8; j++) o[j] += bb[j];
        float* dp = dst + (size_t)n * D_MODEL + o0 + tx*8;
        *(float4*)(dp)     = make_float4(o[0], o[1], o[2], o[3]);
        *(float4*)(dp + 4) = make_float4(o[4], o[5], o[6], o[7]);
    }
}

// ---------------------------------------------------------------------------
// Flash-style causal attention per (b, h, 64-row q tile). 256 threads.
// Q,K staged TRANSPOSED (dd-major, stride 68) for vector LDS in the S-loop.
// KT region reused for P (row-major, stride 65). f32x2 FMAs throughout.
// Smem: QsT[64*68] + Vs[64*64] + KT/P[64*68] = 12800 floats = 51200 B.
// ---------------------------------------------------------------------------
#define QK_LDT 68
#define P_LDS  65
#define ATTN_SMEM_BYTES ((64*QK_LDT + 64*64 + 64*QK_LDT) * 4)

__global__ __launch_bounds__(256) void attn_kernel(float* __restrict__ scores)
{
    extern __shared__ float sm[];
    float* QsT = sm;                       // [dd][row]  stride 68
    float* Vs  = sm + 64*QK_LDT;           // [kk][col]  stride 64
    float* KT  = Vs + 64*64;               // [dd][krow] stride 68; reused as P
    float* Ps  = KT;                       // [qrow][kk] stride 65 (4160 <= 4352)

    const int tid = threadIdx.x;
    const int tx  = tid & 15;
    const int ty  = tid >> 4;
    const int t   = blockIdx.x;            // q tile 0..31
    const int h   = blockIdx.y;
    const int b   = blockIdx.z;
    const int bh  = b * NUM_HEADS + h;

    const float* qbase = g_q + (size_t)bh * SEQ * DQK;
    const float* kbase = g_k + (size_t)bh * SEQ * DQK;
    const float* vbase = g_v + (size_t)bh * SEQ * DQK;
    float* sc = scores + (size_t)bh * SEQ * SEQ;
    const int r0 = t * 64;

    const int lrow = tid >> 2;             // 0..63
    const int dg   = (tid & 3) * 4;        // 0,4,8,12

    // load Q tile transposed: QsT[dd][row]
#pragma unroll
    for (int c = 0; c < 4; c++) {
        int col = dg + c*16;
        float4 qv = *(const float4*)(qbase + (size_t)(r0 + lrow)*DQK + col);
        QsT[(col+0)*QK_LDT + lrow] = qv.x; QsT[(col+1)*QK_LDT + lrow] = qv.y;
        QsT[(col+2)*QK_LDT + lrow] = qv.z; QsT[(col+3)*QK_LDT + lrow] = qv.w;
    }

    float m_i[4], l_i[4];
    u64 O2[4][2];
#pragma unroll
    for (int i = 0; i < 4; i++) {
        m_i[i] = -1e30f; l_i[i] = 0.f;
        O2[i][0] = 0ull; O2[i][1] = 0ull;
    }

    for (int jt = 0; jt <= t; jt++) {
        // load K transposed and V natural
#pragma unroll
        for (int c = 0; c < 4; c++) {
            int col = dg + c*16;
            float4 kv = *(const float4*)(kbase + (size_t)(jt*64 + lrow)*DQK + col);
            KT[(col+0)*QK_LDT + lrow] = kv.x; KT[(col+1)*QK_LDT + lrow] = kv.y;
            KT[(col+2)*QK_LDT + lrow] = kv.z; KT[(col+3)*QK_LDT + lrow] = kv.w;
            float4 vv = *(const float4*)(vbase + (size_t)(jt*64 + lrow)*DQK + col);
            *(float4*)&Vs[lrow*64 + col] = vv;
        }
        __syncthreads();

        // S = Q K^T  (packed over j: s2[i][jp] = cols 2jp, 2jp+1)
        u64 s2[4][2];
#pragma unroll
        for (int i = 0; i < 4; i++) { s2[i][0] = 0ull; s2[i][1] = 0ull; }

#pragma unroll 4
        for (int dd = 0; dd < DQK; dd++) {
            float4 a = *(const float4*)&QsT[dd*QK_LDT + ty*4];
            float4 bq4 = *(const float4*)&KT[dd*QK_LDT + tx*4];
            u64 b0 = pk2(bq4.x, bq4.y);
            u64 b1 = pk2(bq4.z, bq4.w);
            float av[4] = {a.x, a.y, a.z, a.w};
#pragma unroll
            for (int i = 0; i < 4; i++) {
                u64 ad = pk2(av[i], av[i]);
                ffma2(s2[i][0], ad, b0);
                ffma2(s2[i][1], ad, b1);
            }
        }

        // unpack, scale, causal mask, write pre-softmax scores
        float s4[4][4];
#pragma unroll
        for (int i = 0; i < 4; i++) {
            upk2(s2[i][0], s4[i][0], s4[i][1]);
            upk2(s2[i][1], s4[i][2], s4[i][3]);
            int qrow = r0 + ty*4 + i;
#pragma unroll
            for (int j = 0; j < 4; j++) {
                int kcol = jt*64 + tx*4 + j;
                float v = s4[i][j] * 0.125f;           // / sqrt(64)
                v = (kcol <= qrow) ? v : NEG_INF_F;
                s4[i][j] = v;
            }
            *(float4*)&sc[(size_t)qrow*SEQ + jt*64 + tx*4] =
                make_float4(s4[i][0], s4[i][1], s4[i][2], s4[i][3]);
        }
        __syncthreads();   // everyone done reading KT as K

        // online softmax (row state replicated across the 16 tx lanes)
#pragma unroll
        for (int i = 0; i < 4; i++) {
            float tm = fmaxf(fmaxf(s4[i][0], s4[i][1]), fmaxf(s4[i][2], s4[i][3]));
            tm = fmaxf(tm, __shfl_xor_sync(0xffffffffu, tm, 8));
            tm = fmaxf(tm, __shfl_xor_sync(0xffffffffu, tm, 4));
            tm = fmaxf(tm, __shfl_xor_sync(0xffffffffu, tm, 2));
            tm = fmaxf(tm, __shfl_xor_sync(0xffffffffu, tm, 1));
            float mnew = fmaxf(m_i[i], tm);
            float corr = __expf(m_i[i] - mnew);
            float rs = 0.f;
#pragma unroll
            for (int j = 0; j < 4; j++) {
                float p = __expf(s4[i][j] - mnew);     // masked -1e9 -> 0
                s4[i][j] = p;
                rs += p;
            }
            rs += __shfl_xor_sync(0xffffffffu, rs, 8);
            rs += __shfl_xor_sync(0xffffffffu, rs, 4);
            rs += __shfl_xor_sync(0xffffffffu, rs, 2);
            rs += __shfl_xor_sync(0xffffffffu, rs, 1);
            l_i[i] = l_i[i] * corr + rs;
            m_i[i] = mnew;
            u64 cd = pk2(corr, corr);
            O2[i][0] = fmul2(O2[i][0], cd);
            O2[i][1] = fmul2(O2[i][1], cd);
            // store P row-major (stride 65)
#pragma unroll
            for (int j = 0; j < 4; j++)
                Ps[(ty*4+i)*P_LDS + tx*4 + j] = s4[i][j];
        }
        __syncthreads();

        // O += P @ V  (P scalar broadcast, V vectorized, packed over cols)
#pragma unroll 4
        for (int kk = 0; kk < 64; kk++) {
            float4 vvv = *(const float4*)&Vs[kk*64 + tx*4];
            u64 v0 = pk2(vvv.x, vvv.y);
            u64 v1 = pk2(vvv.z, vvv.w);
#pragma unroll
            for (int i = 0; i < 4; i++) {
                float a = Ps[(ty*4+i)*P_LDS + kk];
                u64 ad = pk2(a, a);
                ffma2(O2[i][0], ad, v0);
                ffma2(O2[i][1], ad, v1);
            }
        }
        __syncthreads();   // before next tile's loads overwrite KT/Vs
    }

    // normalize and write attn output in [B,S,H*d] layout
#pragma unroll
    for (int i = 0; i < 4; i++) {
        float inv = 1.0f / l_i[i];
        int row = r0 + ty*4 + i;
        float o[4];
        upk2(O2[i][0], o[0], o[1]);
        upk2(O2[i][1], o[2], o[3]);
        *(float4*)&g_attn[((size_t)(b*SEQ + row))*D_MODEL + h*DQK + tx*4] =
            make_float4(o[0]*inv, o[1]*inv, o[2]*inv, o[3]*inv);
    }

    // fill fully-masked score region (cols >= (t+1)*64) with -1e9
    int rem = 31 - t;
    if (rem > 0) {
        int wf4 = rem * 16;            // float4s per row
        int total = 64 * wf4;
        float4 nv = make_float4(NEG_INF_F, NEG_INF_F, NEG_INF_F, NEG_INF_F);
        for (int idx = tid; idx < total; idx += 256) {
            int rr = idx / wf4;
            int cc = idx - rr * wf4;
            *(float4*)&sc[(size_t)(r0 + rr)*SEQ + (t+1)*64 + cc*4] = nv;
        }
    }
}

extern "C" void kernel_launch(void* const* d_in, const int* in_sizes, int n_in,
                              void* d_out, int out_size)
{
    const float* Q  = (const float*)d_in[0];
    const float* K  = (const float*)d_in[1];
    const float* V  = (const float*)d_in[2];
    // d_in[3] = mask (bool causal) — deterministic, not needed
    const float* Wq = (const float*)d_in[4];
    const float* bq = (const float*)d_in[5];
    const float* Wk = (const float*)d_in[6];
    const float* bk = (const float*)d_in[7];
    const float* Wv = (const float*)d_in[8];
    const float* bv = (const float*)d_in[9];
    const float* Wo = (const float*)d_in[10];
    const float* bo = (const float*)d_in[11];

    float* out    = (float*)d_out;                       // [B,S,768]
    float* scores = out + (size_t)NROWS * D_MODEL;       // [B,H,S,S]

    cudaFuncSetAttribute(attn_kernel,
                         cudaFuncAttributeMaxDynamicSharedMemorySize,
                         ATTN_SMEM_BYTES);

    dim3 qkvgrid(D_MODEL / BN, NROWS / BM, 3);   // (6, 32, 3)
    qkv_kernel<<<qkvgrid, 256>>>(Q, Wq, bq, K, Wk, bk, V, Wv, bv);

    dim3 agrid(SEQ / 64, NUM_HEADS, BATCH);      // (32, 12, 2)
    attn_kernel<<<agrid, 256, ATTN_SMEM_BYTES>>>(scores);

    dim3 ogrid(D_MODEL / BN, NROWS / BM);        // (6, 32)
    oproj_kernel<<<ogrid, 256>>>(Wo, bo, out);
}

// round 10
// speedup vs baseline: 1.1691x; 1.0246x over previous
#include <cuda_runtime.h>

#define D_MODEL   768
#define NUM_HEADS 12
#define DQK       64
#define SEQ       2048
#define BATCH     2
#define NROWS     (BATCH*SEQ)          // 4096
#define NEG_INF_F (-1000000000.0f)

// Scratch (device globals: allocation-free per harness rules)
__device__ float g_q[BATCH*NUM_HEADS*SEQ*DQK];     // [B,H,S,d]
__device__ float g_k[BATCH*NUM_HEADS*SEQ*DQK];
__device__ float g_v[BATCH*NUM_HEADS*SEQ*DQK];
__device__ float g_attn[NROWS*D_MODEL];            // [B,S,H*d]

// ---------------- packed fp32x2 helpers (SASS FFMA2 path) -------------------
typedef unsigned long long u64;

__device__ __forceinline__ u64 pk2(float lo, float hi) {
    u64 r;
    asm("mov.b64 %0, {%1, %2};" : "=l"(r) : "f"(lo), "f"(hi));
    return r;
}
__device__ __forceinline__ void upk2(u64 v, float& lo, float& hi) {
    asm("mov.b64 {%0, %1}, %2;" : "=f"(lo), "=f"(hi) : "l"(v));
}
__device__ __forceinline__ void ffma2(u64& d, u64 a, u64 b) {
    asm("fma.rn.f32x2 %0, %1, %2, %0;" : "+l"(d) : "l"(a), "l"(b));
}
__device__ __forceinline__ u64 fmul2(u64 a, u64 b) {
    u64 r;
    asm("mul.rn.f32x2 %0, %1, %2;" : "=l"(r) : "l"(a), "l"(b));
    return r;
}

// ---------------------------------------------------------------------------
// GEMM core v2: 128x64 output tile, BK=16, 256 threads, 8x4 per thread.
// Accumulators packed over ROW-pairs: acc[ip][j] = {row ty*8+2ip, +2ip+1} x col j.
// A operands come out of smem pre-packed (LDS.128 = 2 u64); only B needs dup movs.
// 16 u64 acc = 32 regs -> 3 CTAs/SM (vs 2 for the 8x8 tile).
// ---------------------------------------------------------------------------
#define BM 128
#define BN 64
#define BKP 16
#define LDX 132   // XsT stride ([k][row], 128 rows)
#define LDW 68    // WsT stride ([k][col], 64 cols)

__device__ __forceinline__ void gemm_core(const float* __restrict__ X,
                                          const float* __restrict__ W,
                                          int n0, int o0,
                                          float* XsT, float* WsT,
                                          u64 acc[4][4])
{
    const int tid  = threadIdx.x;
    const int tx   = tid & 15;
    const int ty   = tid >> 4;
    const int xrow = tid >> 1;          // 0..127
    const int xkg  = (tid & 1) * 8;     // 0 or 8
    const int wrow = tid >> 2;          // 0..63
    const int wkg  = (tid & 3) * 4;     // 0,4,8,12

    const float* Xp = X + (size_t)(n0 + xrow) * D_MODEL + xkg;
    const float* Wp = W + (size_t)(o0 + wrow) * D_MODEL + wkg;

#pragma unroll
    for (int i = 0; i < 4; i++)
#pragma unroll
        for (int j = 0; j < 4; j++) acc[i][j] = 0ull;

#pragma unroll 1
    for (int k0 = 0; k0 < D_MODEL; k0 += BKP) {
        float4 x0 = *(const float4*)(Xp + k0);
        float4 x1 = *(const float4*)(Xp + k0 + 4);
        float4 w0 = *(const float4*)(Wp + k0);
        XsT[(xkg+0)*LDX + xrow] = x0.x; XsT[(xkg+1)*LDX + xrow] = x0.y;
        XsT[(xkg+2)*LDX + xrow] = x0.z; XsT[(xkg+3)*LDX + xrow] = x0.w;
        XsT[(xkg+4)*LDX + xrow] = x1.x; XsT[(xkg+5)*LDX + xrow] = x1.y;
        XsT[(xkg+6)*LDX + xrow] = x1.z; XsT[(xkg+7)*LDX + xrow] = x1.w;
        WsT[(wkg+0)*LDW + wrow] = w0.x; WsT[(wkg+1)*LDW + wrow] = w0.y;
        WsT[(wkg+2)*LDW + wrow] = w0.z; WsT[(wkg+3)*LDW + wrow] = w0.w;
        __syncthreads();

#pragma unroll
        for (int kk = 0; kk < BKP; kk++) {
            const u64* ap = (const u64*)&XsT[kk*LDX + ty*8];
            u64 a2[4] = { ap[0], ap[1], ap[2], ap[3] };    // row pairs, pre-packed
            float4 b = *(const float4*)&WsT[kk*LDW + tx*4];
            u64 bd[4] = { pk2(b.x,b.x), pk2(b.y,b.y), pk2(b.z,b.z), pk2(b.w,b.w) };
#pragma unroll
            for (int ip = 0; ip < 4; ip++)
#pragma unroll
                for (int j = 0; j < 4; j++) ffma2(acc[ip][j], a2[ip], bd[j]);
        }
        __syncthreads();
    }
}

// ---------------------------------------------------------------------------
// Fused Q/K/V projection, head-split output. blockIdx.z picks projection.
// BN=64 -> one output tile == one head exactly.
// ---------------------------------------------------------------------------
__global__ __launch_bounds__(256, 3) void qkv_kernel(
    const float* __restrict__ Qin, const float* __restrict__ Wq, const float* __restrict__ bq,
    const float* __restrict__ Kin, const float* __restrict__ Wk, const float* __restrict__ bk,
    const float* __restrict__ Vin, const float* __restrict__ Wv, const float* __restrict__ bv)
{
    __shared__ float XsT[BKP*LDX];
    __shared__ float WsT[BKP*LDW];

    const int z = blockIdx.z;
    const float* X    = (z == 0) ? Qin : (z == 1) ? Kin : Vin;
    const float* W    = (z == 0) ? Wq  : (z == 1) ? Wk  : Wv;
    const float* bias = (z == 0) ? bq  : (z == 1) ? bk  : bv;
    float* dst        = (z == 0) ? g_q : (z == 1) ? g_k : g_v;

    const int n0 = blockIdx.y * BM;
    const int o0 = blockIdx.x * BN;
    const int tx = threadIdx.x & 15;
    const int ty = threadIdx.x >> 4;
    const int h  = blockIdx.x;          // 64-wide tile == one head

    u64 acc[4][4];
    gemm_core(X, W, n0, o0, XsT, WsT, acc);

    float4 bsv = *(const float4*)(bias + o0 + tx*4);
    float bb[4] = { bsv.x, bsv.y, bsv.z, bsv.w };

#pragma unroll
    for (int ip = 0; ip < 4; ip++) {
        float lo[4], hi[4];
#pragma unroll
        for (int j = 0; j < 4; j++) { upk2(acc[ip][j], lo[j], hi[j]); }
#pragma unroll
        for (int j = 0; j < 4; j++) { lo[j] += bb[j]; hi[j] += bb[j]; }
        int n = n0 + ty*8 + 2*ip;
        int b0i = n >> 11, s0 = n & (SEQ-1);
        int b1i = (n+1) >> 11, s1 = (n+1) & (SEQ-1);
        *(float4*)&dst[(((size_t)(b0i*NUM_HEADS + h))*SEQ + s0)*DQK + tx*4] =
            make_float4(lo[0], lo[1], lo[2], lo[3]);
        *(float4*)&dst[(((size_t)(b1i*NUM_HEADS + h))*SEQ + s1)*DQK + tx*4] =
            make_float4(hi[0], hi[1], hi[2], hi[3]);
    }
}

// ---------------------------------------------------------------------------
// Output projection: out = g_attn @ Wo^T + bo, flat [4096,768].
// ---------------------------------------------------------------------------
__global__ __launch_bounds__(256, 3) void oproj_kernel(const float* __restrict__ W,
                                                       const float* __restrict__ bias,
                                                       float* __restrict__ dst)
{
    __shared__ float XsT[BKP*LDX];
    __shared__ float WsT[BKP*LDW];

    const int n0 = blockIdx.y * BM;
    const int o0 = blockIdx.x * BN;
    const int tx = threadIdx.x & 15;
    const int ty = threadIdx.x >> 4;

    u64 acc[4][4];
    gemm_core(g_attn, W, n0, o0, XsT, WsT, acc);

    float4 bsv = *(const float4*)(bias + o0 + tx*4);
    float bb[4] = { bsv.x, bsv.y, bsv.z, bsv.w };

#pragma unroll
    for (int ip = 0; ip < 4; ip++) {
        float lo[4], hi[4];
#pragma unroll
        for (int j = 0; j < 4; j++) { upk2(acc[ip][j], lo[j], hi[j]); }
#pragma unroll
        for (int j = 0; j < 4; j++) { lo[j] += bb[j]; hi[j] += bb[j]; }
        int n = n0 + ty*8 + 2*ip;
        *(float4*)&dst[(size_t)n * D_MODEL + o0 + tx*4] =
            make_float4(lo[0], lo[1], lo[2], lo[3]);
        *(float4*)&dst[(size_t)(n+1) * D_MODEL + o0 + tx*4] =
            make_float4(hi[0], hi[1], hi[2], hi[3]);
    }
}

// ---------------------------------------------------------------------------
// Flash-style causal attention per (b, h, 64-row q tile). 256 threads.
// Heavy-first block order: t = 31 - blockIdx.x (LPT scheduling for the
// triangular workload; pure work->block permutation, no numeric change).
// ---------------------------------------------------------------------------
#define QK_LDT 68
#define P_LDS  65
#define ATTN_SMEM_BYTES ((64*QK_LDT + 64*64 + 64*QK_LDT) * 4)

__global__ __launch_bounds__(256) void attn_kernel(float* __restrict__ scores)
{
    extern __shared__ float sm[];
    float* QsT = sm;                       // [dd][row]  stride 68
    float* Vs  = sm + 64*QK_LDT;           // [kk][col]  stride 64
    float* KT  = Vs + 64*64;               // [dd][krow] stride 68; reused as P
    float* Ps  = KT;                       // [qrow][kk] stride 65

    const int tid = threadIdx.x;
    const int tx  = tid & 15;
    const int ty  = tid >> 4;
    const int t   = (SEQ/64 - 1) - blockIdx.x;   // heavy tiles launch first
    const int h   = blockIdx.y;
    const int b   = blockIdx.z;
    const int bh  = b * NUM_HEADS + h;

    const float* qbase = g_q + (size_t)bh * SEQ * DQK;
    const float* kbase = g_k + (size_t)bh * SEQ * DQK;
    const float* vbase = g_v + (size_t)bh * SEQ * DQK;
    float* sc = scores + (size_t)bh * SEQ * SEQ;
    const int r0 = t * 64;

    const int lrow = tid >> 2;             // 0..63
    const int dg   = (tid & 3) * 4;        // 0,4,8,12

#pragma unroll
    for (int c = 0; c < 4; c++) {
        int col = dg + c*16;
        float4 qv = *(const float4*)(qbase + (size_t)(r0 + lrow)*DQK + col);
        QsT[(col+0)*QK_LDT + lrow] = qv.x; QsT[(col+1)*QK_LDT + lrow] = qv.y;
        QsT[(col+2)*QK_LDT + lrow] = qv.z; QsT[(col+3)*QK_LDT + lrow] = qv.w;
    }

    float m_i[4], l_i[4];
    u64 O2[4][2];
#pragma unroll
    for (int i = 0; i < 4; i++) {
        m_i[i] = -1e30f; l_i[i] = 0.f;
        O2[i][0] = 0ull; O2[i][1] = 0ull;
    }

    for (int jt = 0; jt <= t; jt++) {
#pragma unroll
        for (int c = 0; c < 4; c++) {
            int col = dg + c*16;
            float4 kv = *(const float4*)(kbase + (size_t)(jt*64 + lrow)*DQK + col);
            KT[(col+0)*QK_LDT + lrow] = kv.x; KT[(col+1)*QK_LDT + lrow] = kv.y;
            KT[(col+2)*QK_LDT + lrow] = kv.z; KT[(col+3)*QK_LDT + lrow] = kv.w;
            float4 vv = *(const float4*)(vbase + (size_t)(jt*64 + lrow)*DQK + col);
            *(float4*)&Vs[lrow*64 + col] = vv;
        }
        __syncthreads();

        u64 s2[4][2];
#pragma unroll
        for (int i = 0; i < 4; i++) { s2[i][0] = 0ull; s2[i][1] = 0ull; }

#pragma unroll 4
        for (int dd = 0; dd < DQK; dd++) {
            float4 a = *(const float4*)&QsT[dd*QK_LDT + ty*4];
            float4 bq4 = *(const float4*)&KT[dd*QK_LDT + tx*4];
            u64 b0 = pk2(bq4.x, bq4.y);
            u64 b1 = pk2(bq4.z, bq4.w);
            float av[4] = {a.x, a.y, a.z, a.w};
#pragma unroll
            for (int i = 0; i < 4; i++) {
                u64 ad = pk2(av[i], av[i]);
                ffma2(s2[i][0], ad, b0);
                ffma2(s2[i][1], ad, b1);
            }
        }

        float s4[4][4];
#pragma unroll
        for (int i = 0; i < 4; i++) {
            upk2(s2[i][0], s4[i][0], s4[i][1]);
            upk2(s2[i][1], s4[i][2], s4[i][3]);
            int qrow = r0 + ty*4 + i;
#pragma unroll
            for (int j = 0; j < 4; j++) {
                int kcol = jt*64 + tx*4 + j;
                float v = s4[i][j] * 0.125f;
                v = (kcol <= qrow) ? v : NEG_INF_F;
                s4[i][j] = v;
            }
            *(float4*)&sc[(size_t)qrow*SEQ + jt*64 + tx*4] =
                make_float4(s4[i][0], s4[i][1], s4[i][2], s4[i][3]);
        }
        __syncthreads();

#pragma unroll
        for (int i = 0; i < 4; i++) {
            float tm = fmaxf(fmaxf(s4[i][0], s4[i][1]), fmaxf(s4[i][2], s4[i][3]));
            tm = fmaxf(tm, __shfl_xor_sync(0xffffffffu, tm, 8));
            tm = fmaxf(tm, __shfl_xor_sync(0xffffffffu, tm, 4));
            tm = fmaxf(tm, __shfl_xor_sync(0xffffffffu, tm, 2));
            tm = fmaxf(tm, __shfl_xor_sync(0xffffffffu, tm, 1));
            float mnew = fmaxf(m_i[i], tm);
            float corr = __expf(m_i[i] - mnew);
            float rs = 0.f;
#pragma unroll
            for (int j = 0; j < 4; j++) {
                float p = __expf(s4[i][j] - mnew);
                s4[i][j] = p;
                rs += p;
            }
            rs += __shfl_xor_sync(0xffffffffu, rs, 8);
            rs += __shfl_xor_sync(0xffffffffu, rs, 4);
            rs += __shfl_xor_sync(0xffffffffu, rs, 2);
            rs += __shfl_xor_sync(0xffffffffu, rs, 1);
            l_i[i] = l_i[i] * corr + rs;
            m_i[i] = mnew;
            u64 cd = pk2(corr, corr);
            O2[i][0] = fmul2(O2[i][0], cd);
            O2[i][1] = fmul2(O2[i][1], cd);
#pragma unroll
            for (int j = 0; j < 4; j++)
                Ps[(ty*4+i)*P_LDS + tx*4 + j] = s4[i][j];
        }
        __syncthreads();

#pragma unroll 4
        for (int kk = 0; kk < 64; kk++) {
            float4 vvv = *(const float4*)&Vs[kk*64 + tx*4];
            u64 v0 = pk2(vvv.x, vvv.y);
            u64 v1 = pk2(vvv.z, vvv.w);
#pragma unroll
            for (int i = 0; i < 4; i++) {
                float a = Ps[(ty*4+i)*P_LDS + kk];
                u64 ad = pk2(a, a);
                ffma2(O2[i][0], ad, v0);
                ffma2(O2[i][1], ad, v1);
            }
        }
        __syncthreads();
    }

#pragma unroll
    for (int i = 0; i < 4; i++) {
        float inv = 1.0f / l_i[i];
        int row = r0 + ty*4 + i;
        float o[4];
        upk2(O2[i][0], o[0], o[1]);
        upk2(O2[i][1], o[2], o[3]);
        *(float4*)&g_attn[((size_t)(b*SEQ + row))*D_MODEL + h*DQK + tx*4] =
            make_float4(o[0]*inv, o[1]*inv, o[2]*inv, o[3]*inv);
    }

    int rem = 31 - t;
    if (rem > 0) {
        int wf4 = rem * 16;
        int total = 64 * wf4;
        float4 nv = make_float4(NEG_INF_F, NEG_INF_F, NEG_INF_F, NEG_INF_F);
        for (int idx = tid; idx < total; idx += 256) {
            int rr = idx / wf4;
            int cc = idx - rr * wf4;
            *(float4*)&sc[(size_t)(r0 + rr)*SEQ + (t+1)*64 + cc*4] = nv;
        }
    }
}

extern "C" void kernel_launch(void* const* d_in, const int* in_sizes, int n_in,
                              void* d_out, int out_size)
{
    const float* Q  = (const float*)d_in[0];
    const float* K  = (const float*)d_in[1];
    const float* V  = (const float*)d_in[2];
    // d_in[3] = mask (bool causal) — deterministic, not needed
    const float* Wq = (const float*)d_in[4];
    const float* bq = (const float*)d_in[5];
    const float* Wk = (const float*)d_in[6];
    const float* bk = (const float*)d_in[7];
    const float* Wv = (const float*)d_in[8];
    const float* bv = (const float*)d_in[9];
    const float* Wo = (const float*)d_in[10];
    const float* bo = (const float*)d_in[11];

    float* out    = (float*)d_out;                       // [B,S,768]
    float* scores = out + (size_t)NROWS * D_MODEL;       // [B,H,S,S]

    cudaFuncSetAttribute(attn_kernel,
                         cudaFuncAttributeMaxDynamicSharedMemorySize,
                         ATTN_SMEM_BYTES);

    dim3 qkvgrid(D_MODEL / BN, NROWS / BM, 3);   // (12, 32, 3)
    qkv_kernel<<<qkvgrid, 256>>>(Q, Wq, bq, K, Wk, bk, V, Wv, bv);

    dim3 agrid(SEQ / 64, NUM_HEADS, BATCH);      // (32, 12, 2)
    attn_kernel<<<agrid, 256, ATTN_SMEM_BYTES>>>(scores);

    dim3 ogrid(D_MODEL / BN, NROWS / BM);        // (12, 32)
    oproj_kernel<<<ogrid, 256>>>(Wo, bo, out);
}

// round 11
// speedup vs baseline: 1.2194x; 1.0430x over previous
#include <cuda_runtime.h>

#define D_MODEL   768
#define NUM_HEADS 12
#define DQK       64
#define SEQ       2048
#define BATCH     2
#define NROWS     (BATCH*SEQ)          // 4096
#define NEG_INF_F (-1000000000.0f)

// Scratch (device globals: allocation-free per harness rules)
__device__ float g_q[BATCH*NUM_HEADS*SEQ*DQK];     // [B,H,S,d]
__device__ float g_k[BATCH*NUM_HEADS*SEQ*DQK];
__device__ float g_v[BATCH*NUM_HEADS*SEQ*DQK];
__device__ float g_attn[NROWS*D_MODEL];            // [B,S,H*d]

// ---------------- packed fp32x2 helpers (SASS FFMA2 path) -------------------
typedef unsigned long long u64;

__device__ __forceinline__ u64 pk2(float lo, float hi) {
    u64 r;
    asm("mov.b64 %0, {%1, %2};" : "=l"(r) : "f"(lo), "f"(hi));
    return r;
}
__device__ __forceinline__ void upk2(u64 v, float& lo, float& hi) {
    asm("mov.b64 {%0, %1}, %2;" : "=f"(lo), "=f"(hi) : "l"(v));
}
__device__ __forceinline__ void ffma2(u64& d, u64 a, u64 b) {
    asm("fma.rn.f32x2 %0, %1, %2, %0;" : "+l"(d) : "l"(a), "l"(b));
}
__device__ __forceinline__ u64 fmul2(u64 a, u64 b) {
    u64 r;
    asm("mul.rn.f32x2 %0, %1, %2;" : "=l"(r) : "l"(a), "l"(b));
    return r;
}

// ---------------------------------------------------------------------------
// GEMM core v3: 128x64 tile, BK=16, 256 threads, 8x4/thread, row-pair-packed
// FFMA2 accumulators + GMEM->register PREFETCH (next phase's loads issued
// right after the sync, hidden behind the 16-kk compute).
// ---------------------------------------------------------------------------
#define BM 128
#define BN 64
#define BKP 16
#define LDX 132   // XsT stride ([k][row], 128 rows)
#define LDW 68    // WsT stride ([k][col], 64 cols)

__device__ __forceinline__ void gemm_core(const float* __restrict__ X,
                                          const float* __restrict__ W,
                                          int n0, int o0,
                                          float* XsT, float* WsT,
                                          u64 acc[4][4])
{
    const int tid  = threadIdx.x;
    const int tx   = tid & 15;
    const int ty   = tid >> 4;
    const int xrow = tid >> 1;          // 0..127
    const int xkg  = (tid & 1) * 8;     // 0 or 8
    const int wrow = tid >> 2;          // 0..63
    const int wkg  = (tid & 3) * 4;     // 0,4,8,12

    const float* Xp = X + (size_t)(n0 + xrow) * D_MODEL + xkg;
    const float* Wp = W + (size_t)(o0 + wrow) * D_MODEL + wkg;

#pragma unroll
    for (int i = 0; i < 4; i++)
#pragma unroll
        for (int j = 0; j < 4; j++) acc[i][j] = 0ull;

    // stage phase 0
    float4 x0 = *(const float4*)(Xp);
    float4 x1 = *(const float4*)(Xp + 4);
    float4 w0 = *(const float4*)(Wp);

#pragma unroll 1
    for (int k0 = 0; k0 < D_MODEL; k0 += BKP) {
        XsT[(xkg+0)*LDX + xrow] = x0.x; XsT[(xkg+1)*LDX + xrow] = x0.y;
        XsT[(xkg+2)*LDX + xrow] = x0.z; XsT[(xkg+3)*LDX + xrow] = x0.w;
        XsT[(xkg+4)*LDX + xrow] = x1.x; XsT[(xkg+5)*LDX + xrow] = x1.y;
        XsT[(xkg+6)*LDX + xrow] = x1.z; XsT[(xkg+7)*LDX + xrow] = x1.w;
        WsT[(wkg+0)*LDW + wrow] = w0.x; WsT[(wkg+1)*LDW + wrow] = w0.y;
        WsT[(wkg+2)*LDW + wrow] = w0.z; WsT[(wkg+3)*LDW + wrow] = w0.w;
        __syncthreads();

        // prefetch next phase (latency hidden behind the kk compute)
        if (k0 + BKP < D_MODEL) {
            x0 = *(const float4*)(Xp + k0 + BKP);
            x1 = *(const float4*)(Xp + k0 + BKP + 4);
            w0 = *(const float4*)(Wp + k0 + BKP);
        }

#pragma unroll
        for (int kk = 0; kk < BKP; kk++) {
            const u64* ap = (const u64*)&XsT[kk*LDX + ty*8];
            u64 a2[4] = { ap[0], ap[1], ap[2], ap[3] };    // row pairs, pre-packed
            float4 b = *(const float4*)&WsT[kk*LDW + tx*4];
            u64 bd[4] = { pk2(b.x,b.x), pk2(b.y,b.y), pk2(b.z,b.z), pk2(b.w,b.w) };
#pragma unroll
            for (int ip = 0; ip < 4; ip++)
#pragma unroll
                for (int j = 0; j < 4; j++) ffma2(acc[ip][j], a2[ip], bd[j]);
        }
        __syncthreads();
    }
}

// ---------------------------------------------------------------------------
// Fused Q/K/V projection, head-split output. blockIdx.z picks projection.
// ---------------------------------------------------------------------------
__global__ __launch_bounds__(256, 3) void qkv_kernel(
    const float* __restrict__ Qin, const float* __restrict__ Wq, const float* __restrict__ bq,
    const float* __restrict__ Kin, const float* __restrict__ Wk, const float* __restrict__ bk,
    const float* __restrict__ Vin, const float* __restrict__ Wv, const float* __restrict__ bv)
{
    __shared__ float XsT[BKP*LDX];
    __shared__ float WsT[BKP*LDW];

    const int z = blockIdx.z;
    const float* X    = (z == 0) ? Qin : (z == 1) ? Kin : Vin;
    const float* W    = (z == 0) ? Wq  : (z == 1) ? Wk  : Wv;
    const float* bias = (z == 0) ? bq  : (z == 1) ? bk  : bv;
    float* dst        = (z == 0) ? g_q : (z == 1) ? g_k : g_v;

    const int n0 = blockIdx.y * BM;
    const int o0 = blockIdx.x * BN;
    const int tx = threadIdx.x & 15;
    const int ty = threadIdx.x >> 4;
    const int h  = blockIdx.x;          // 64-wide tile == one head

    u64 acc[4][4];
    gemm_core(X, W, n0, o0, XsT, WsT, acc);

    float4 bsv = *(const float4*)(bias + o0 + tx*4);
    float bb[4] = { bsv.x, bsv.y, bsv.z, bsv.w };

#pragma unroll
    for (int ip = 0; ip < 4; ip++) {
        float lo[4], hi[4];
#pragma unroll
        for (int j = 0; j < 4; j++) { upk2(acc[ip][j], lo[j], hi[j]); }
#pragma unroll
        for (int j = 0; j < 4; j++) { lo[j] += bb[j]; hi[j] += bb[j]; }
        int n = n0 + ty*8 + 2*ip;
        int b0i = n >> 11, s0 = n & (SEQ-1);
        int b1i = (n+1) >> 11, s1 = (n+1) & (SEQ-1);
        *(float4*)&dst[(((size_t)(b0i*NUM_HEADS + h))*SEQ + s0)*DQK + tx*4] =
            make_float4(lo[0], lo[1], lo[2], lo[3]);
        *(float4*)&dst[(((size_t)(b1i*NUM_HEADS + h))*SEQ + s1)*DQK + tx*4] =
            make_float4(hi[0], hi[1], hi[2], hi[3]);
    }
}

// ---------------------------------------------------------------------------
// Output projection: out = g_attn @ Wo^T + bo, flat [4096,768].
// ---------------------------------------------------------------------------
__global__ __launch_bounds__(256, 3) void oproj_kernel(const float* __restrict__ W,
                                                       const float* __restrict__ bias,
                                                       float* __restrict__ dst)
{
    __shared__ float XsT[BKP*LDX];
    __shared__ float WsT[BKP*LDW];

    const int n0 = blockIdx.y * BM;
    const int o0 = blockIdx.x * BN;
    const int tx = threadIdx.x & 15;
    const int ty = threadIdx.x >> 4;

    u64 acc[4][4];
    gemm_core(g_attn, W, n0, o0, XsT, WsT, acc);

    float4 bsv = *(const float4*)(bias + o0 + tx*4);
    float bb[4] = { bsv.x, bsv.y, bsv.z, bsv.w };

#pragma unroll
    for (int ip = 0; ip < 4; ip++) {
        float lo[4], hi[4];
#pragma unroll
        for (int j = 0; j < 4; j++) { upk2(acc[ip][j], lo[j], hi[j]); }
#pragma unroll
        for (int j = 0; j < 4; j++) { lo[j] += bb[j]; hi[j] += bb[j]; }
        int n = n0 + ty*8 + 2*ip;
        *(float4*)&dst[(size_t)n * D_MODEL + o0 + tx*4] =
            make_float4(lo[0], lo[1], lo[2], lo[3]);
        *(float4*)&dst[(size_t)(n+1) * D_MODEL + o0 + tx*4] =
            make_float4(hi[0], hi[1], hi[2], hi[3]);
    }
}

// ---------------------------------------------------------------------------
// Flash-style causal attention per (b, h, 64-row q tile). 256 threads.
// Heavy-first block order (t = 31 - blockIdx.x) + K/V register prefetch:
// the jt+1 tile's LDGs issue right after the post-STS sync, hidden behind
// QK + softmax + PV of tile jt.
// ---------------------------------------------------------------------------
#define QK_LDT 68
#define P_LDS  65
#define ATTN_SMEM_BYTES ((64*QK_LDT + 64*64 + 64*QK_LDT) * 4)

__global__ __launch_bounds__(256) void attn_kernel(float* __restrict__ scores)
{
    extern __shared__ float sm[];
    float* QsT = sm;                       // [dd][row]  stride 68
    float* Vs  = sm + 64*QK_LDT;           // [kk][col]  stride 64
    float* KT  = Vs + 64*64;               // [dd][krow] stride 68; reused as P
    float* Ps  = KT;                       // [qrow][kk] stride 65

    const int tid = threadIdx.x;
    const int tx  = tid & 15;
    const int ty  = tid >> 4;
    const int t   = (SEQ/64 - 1) - blockIdx.x;   // heavy tiles launch first
    const int h   = blockIdx.y;
    const int b   = blockIdx.z;
    const int bh  = b * NUM_HEADS + h;

    const float* qbase = g_q + (size_t)bh * SEQ * DQK;
    const float* kbase = g_k + (size_t)bh * SEQ * DQK;
    const float* vbase = g_v + (size_t)bh * SEQ * DQK;
    float* sc = scores + (size_t)bh * SEQ * SEQ;
    const int r0 = t * 64;

    const int lrow = tid >> 2;             // 0..63
    const int dg   = (tid & 3) * 4;        // 0,4,8,12

#pragma unroll
    for (int c = 0; c < 4; c++) {
        int col = dg + c*16;
        float4 qv = *(const float4*)(qbase + (size_t)(r0 + lrow)*DQK + col);
        QsT[(col+0)*QK_LDT + lrow] = qv.x; QsT[(col+1)*QK_LDT + lrow] = qv.y;
        QsT[(col+2)*QK_LDT + lrow] = qv.z; QsT[(col+3)*QK_LDT + lrow] = qv.w;
    }

    float m_i[4], l_i[4];
    u64 O2[4][2];
#pragma unroll
    for (int i = 0; i < 4; i++) {
        m_i[i] = -1e30f; l_i[i] = 0.f;
        O2[i][0] = 0ull; O2[i][1] = 0ull;
    }

    // stage K/V tile jt=0 in registers
    float4 kpre[4], vpre[4];
#pragma unroll
    for (int c = 0; c < 4; c++) {
        int col = dg + c*16;
        kpre[c] = *(const float4*)(kbase + (size_t)lrow*DQK + col);
        vpre[c] = *(const float4*)(vbase + (size_t)lrow*DQK + col);
    }

    for (int jt = 0; jt <= t; jt++) {
        // commit staged K/V to smem
#pragma unroll
        for (int c = 0; c < 4; c++) {
            int col = dg + c*16;
            KT[(col+0)*QK_LDT + lrow] = kpre[c].x; KT[(col+1)*QK_LDT + lrow] = kpre[c].y;
            KT[(col+2)*QK_LDT + lrow] = kpre[c].z; KT[(col+3)*QK_LDT + lrow] = kpre[c].w;
            *(float4*)&Vs[lrow*64 + col] = vpre[c];
        }
        __syncthreads();

        // prefetch next K/V tile (hidden behind QK + softmax + PV)
        if (jt < t) {
#pragma unroll
            for (int c = 0; c < 4; c++) {
                int col = dg + c*16;
                kpre[c] = *(const float4*)(kbase + (size_t)((jt+1)*64 + lrow)*DQK + col);
                vpre[c] = *(const float4*)(vbase + (size_t)((jt+1)*64 + lrow)*DQK + col);
            }
        }

        u64 s2[4][2];
#pragma unroll
        for (int i = 0; i < 4; i++) { s2[i][0] = 0ull; s2[i][1] = 0ull; }

#pragma unroll 4
        for (int dd = 0; dd < DQK; dd++) {
            float4 a = *(const float4*)&QsT[dd*QK_LDT + ty*4];
            float4 bq4 = *(const float4*)&KT[dd*QK_LDT + tx*4];
            u64 b0 = pk2(bq4.x, bq4.y);
            u64 b1 = pk2(bq4.z, bq4.w);
            float av[4] = {a.x, a.y, a.z, a.w};
#pragma unroll
            for (int i = 0; i < 4; i++) {
                u64 ad = pk2(av[i], av[i]);
                ffma2(s2[i][0], ad, b0);
                ffma2(s2[i][1], ad, b1);
            }
        }

        float s4[4][4];
#pragma unroll
        for (int i = 0; i < 4; i++) {
            upk2(s2[i][0], s4[i][0], s4[i][1]);
            upk2(s2[i][1], s4[i][2], s4[i][3]);
            int qrow = r0 + ty*4 + i;
#pragma unroll
            for (int j = 0; j < 4; j++) {
                int kcol = jt*64 + tx*4 + j;
                float v = s4[i][j] * 0.125f;
                v = (kcol <= qrow) ? v : NEG_INF_F;
                s4[i][j] = v;
            }
            *(float4*)&sc[(size_t)qrow*SEQ + jt*64 + tx*4] =
                make_float4(s4[i][0], s4[i][1], s4[i][2], s4[i][3]);
        }
        __syncthreads();

#pragma unroll
        for (int i = 0; i < 4; i++) {
            float tm = fmaxf(fmaxf(s4[i][0], s4[i][1]), fmaxf(s4[i][2], s4[i][3]));
            tm = fmaxf(tm, __shfl_xor_sync(0xffffffffu, tm, 8));
            tm = fmaxf(tm, __shfl_xor_sync(0xffffffffu, tm, 4));
            tm = fmaxf(tm, __shfl_xor_sync(0xffffffffu, tm, 2));
            tm = fmaxf(tm, __shfl_xor_sync(0xffffffffu, tm, 1));
            float mnew = fmaxf(m_i[i], tm);
            float corr = __expf(m_i[i] - mnew);
            float rs = 0.f;
#pragma unroll
            for (int j = 0; j < 4; j++) {
                float p = __expf(s4[i][j] - mnew);
                s4[i][j] = p;
                rs += p;
            }
            rs += __shfl_xor_sync(0xffffffffu, rs, 8);
            rs += __shfl_xor_sync(0xffffffffu, rs, 4);
            rs += __shfl_xor_sync(0xffffffffu, rs, 2);
            rs += __shfl_xor_sync(0xffffffffu, rs, 1);
            l_i[i] = l_i[i] * corr + rs;
            m_i[i] = mnew;
            u64 cd = pk2(corr, corr);
            O2[i][0] = fmul2(O2[i][0], cd);
            O2[i][1] = fmul2(O2[i][1], cd);
#pragma unroll
            for (int j = 0; j < 4; j++)
                Ps[(ty*4+i)*P_LDS + tx*4 + j] = s4[i][j];
        }
        __syncthreads();

#pragma unroll 4
        for (int kk = 0; kk < 64; kk++) {
            float4 vvv = *(const float4*)&Vs[kk*64 + tx*4];
            u64 v0 = pk2(vvv.x, vvv.y);
            u64 v1 = pk2(vvv.z, vvv.w);
#pragma unroll
            for (int i = 0; i < 4; i++) {
                float a = Ps[(ty*4+i)*P_LDS + kk];
                u64 ad = pk2(a, a);
                ffma2(O2[i][0], ad, v0);
                ffma2(O2[i][1], ad, v1);
            }
        }
        __syncthreads();
    }

#pragma unroll
    for (int i = 0; i < 4; i++) {
        float inv = 1.0f / l_i[i];
        int row = r0 + ty*4 + i;
        float o[4];
        upk2(O2[i][0], o[0], o[1]);
        upk2(O2[i][1], o[2], o[3]);
        *(float4*)&g_attn[((size_t)(b*SEQ + row))*D_MODEL + h*DQK + tx*4] =
            make_float4(o[0]*inv, o[1]*inv, o[2]*inv, o[3]*inv);
    }

    int rem = 31 - t;
    if (rem > 0) {
        int wf4 = rem * 16;
        int total = 64 * wf4;
        float4 nv = make_float4(NEG_INF_F, NEG_INF_F, NEG_INF_F, NEG_INF_F);
        for (int idx = tid; idx < total; idx += 256) {
            int rr = idx / wf4;
            int cc = idx - rr * wf4;
            *(float4*)&sc[(size_t)(r0 + rr)*SEQ + (t+1)*64 + cc*4] = nv;
        }
    }
}

extern "C" void kernel_launch(void* const* d_in, const int* in_sizes, int n_in,
                              void* d_out, int out_size)
{
    const float* Q  = (const float*)d_in[0];
    const float* K  = (const float*)d_in[1];
    const float* V  = (const float*)d_in[2];
    // d_in[3] = mask (bool causal) — deterministic, not needed
    const float* Wq = (const float*)d_in[4];
    const float* bq = (const float*)d_in[5];
    const float* Wk = (const float*)d_in[6];
    const float* bk = (const float*)d_in[7];
    const float* Wv = (const float*)d_in[8];
    const float* bv = (const float*)d_in[9];
    const float* Wo = (const float*)d_in[10];
    const float* bo = (const float*)d_in[11];

    float* out    = (float*)d_out;                       // [B,S,768]
    float* scores = out + (size_t)NROWS * D_MODEL;       // [B,H,S,S]

    cudaFuncSetAttribute(attn_kernel,
                         cudaFuncAttributeMaxDynamicSharedMemorySize,
                         ATTN_SMEM_BYTES);

    dim3 qkvgrid(D_MODEL / BN, NROWS / BM, 3);   // (12, 32, 3)
    qkv_kernel<<<qkvgrid, 256>>>(Q, Wq, bq, K, Wk, bk, V, Wv, bv);

    dim3 agrid(SEQ / 64, NUM_HEADS, BATCH);      // (32, 12, 2)
    attn_kernel<<<agrid, 256, ATTN_SMEM_BYTES>>>(scores);

    dim3 ogrid(D_MODEL / BN, NROWS / BM);        // (12, 32)
    oproj_kernel<<<ogrid, 256>>>(Wo, bo, out);
}

// round 15
// speedup vs baseline: 1.5701x; 1.2876x over previous
#include <cuda_runtime.h>
#include <cuda_bf16.h>
#include <cstdint>

#define D_MODEL   768
#define NUM_HEADS 12
#define DQK       64
#define SEQ       2048
#define BATCH     2
#define NROWS     (BATCH*SEQ)          // 4096
#define NEG_INF_F (-1000000000.0f)

// ---------------- fp32 scratch ----------------
__device__ float g_q[BATCH*NUM_HEADS*SEQ*DQK];     // [B,H,S,d]
__device__ float g_k[BATCH*NUM_HEADS*SEQ*DQK];
__device__ float g_v[BATCH*NUM_HEADS*SEQ*DQK];
__device__ float g_attn[NROWS*D_MODEL];            // [B,S,H*d]

// ---------------- bf16-split scratch ----------------
#define XOFF (NROWS*D_MODEL)        // 3145728
#define WOFF (D_MODEL*D_MODEL)      // 589824
__device__ __nv_bfloat16 g_xhi[3*XOFF], g_xlo[3*XOFF];   // Q,K,V inputs
__device__ __nv_bfloat16 g_whi[4*WOFF], g_wlo[4*WOFF];   // Wq,Wk,Wv,Wo
__device__ __nv_bfloat16 g_ahi[XOFF],  g_alo[XOFF];      // attn output

// ---------------- packed fp32x2 helpers (attn kernel) ----------------
typedef unsigned long long u64;
__device__ __forceinline__ u64 pk2(float lo, float hi) {
    u64 r; asm("mov.b64 %0, {%1, %2};" : "=l"(r) : "f"(lo), "f"(hi)); return r;
}
__device__ __forceinline__ void upk2(u64 v, float& lo, float& hi) {
    asm("mov.b64 {%0, %1}, %2;" : "=f"(lo), "=f"(hi) : "l"(v));
}
__device__ __forceinline__ void ffma2(u64& d, u64 a, u64 b) {
    asm("fma.rn.f32x2 %0, %1, %2, %0;" : "+l"(d) : "l"(a), "l"(b));
}
__device__ __forceinline__ u64 fmul2(u64 a, u64 b) {
    u64 r; asm("mul.rn.f32x2 %0, %1, %2;" : "=l"(r) : "l"(a), "l"(b)); return r;
}

// ---------------- warp-mma helpers (baseline PTX, no arch-a features) -------
__device__ __forceinline__ uint32_t smem_u32(const void* p) {
    uint32_t a;
    asm("{ .reg .u64 t; cvta.to.shared.u64 t, %1; cvt.u32.u64 %0, t; }" : "=r"(a) : "l"(p));
    return a;
}
#define SWZ128(o) ((o) ^ (((o) >> 3) & 0x70))

#define LDSM4(r, addr) \
    asm volatile("ldmatrix.sync.aligned.m8n8.x4.shared.b16 {%0,%1,%2,%3}, [%4];" \
        : "=r"((r)[0]), "=r"((r)[1]), "=r"((r)[2]), "=r"((r)[3]) : "r"(addr))

#define MMA16816(c, a, b0, b1) \
    asm volatile("mma.sync.aligned.m16n8k16.row.col.f32.bf16.bf16.f32 " \
        "{%0,%1,%2,%3}, {%4,%5,%6,%7}, {%8,%9}, {%0,%1,%2,%3};" \
        : "+f"((c)[0]), "+f"((c)[1]), "+f"((c)[2]), "+f"((c)[3]) \
        : "r"((a)[0]), "r"((a)[1]), "r"((a)[2]), "r"((a)[3]), "r"(b0), "r"(b1))

// ---------------------------------------------------------------------------
// fp32 -> bf16 hi/lo split. which: 0-2 = Q/K/V in, 3-6 = Wq/Wk/Wv/Wo, 7 = g_attn
// ---------------------------------------------------------------------------
__global__ __launch_bounds__(256) void convert_kernel(const float* __restrict__ src,
                                                      int n, int which)
{
    __nv_bfloat16 *hi, *lo;
    if (which < 3)      { hi = g_xhi + which*XOFF;     lo = g_xlo + which*XOFF; }
    else if (which < 7) { hi = g_whi + (which-3)*WOFF; lo = g_wlo + (which-3)*WOFF; }
    else                { hi = g_ahi; lo = g_alo; src = g_attn; }

    int i = (blockIdx.x * 256 + threadIdx.x) * 2;
    if (i < n) {
        float2 x = *(const float2*)(src + i);
        __nv_bfloat16 h0 = __float2bfloat16(x.x);
        __nv_bfloat16 h1 = __float2bfloat16(x.y);
        __nv_bfloat16 l0 = __float2bfloat16(x.x - __bfloat162float(h0));
        __nv_bfloat16 l1 = __float2bfloat16(x.y - __bfloat162float(h1));
        __nv_bfloat162 hv; hv.x = h0; hv.y = h1;
        __nv_bfloat162 lv; lv.x = l0; lv.y = l1;
        *(__nv_bfloat162*)(hi + i) = hv;
        *(__nv_bfloat162*)(lo + i) = lv;
    }
}

// ---------------------------------------------------------------------------
// Warp-mma projection GEMM: D[128,64] = X[128,768] @ W^T + bias.
// bf16-split 3-term (Xhi*Whi + Xhi*Wlo + Xlo*Whi), fp32 accumulators.
// 8 warps in 4x2: each warp 32x32 output = 2 m-tiles x 4 n-tiles of m16n8k16.
// K staged 64/phase in SW128 smem; fragments via ldmatrix.x4.
// qkv mode (is_oproj=0): grid (12,32,3), z selects projection, head-split dst.
// oproj mode: grid (12,32,1), flat dst.
// ---------------------------------------------------------------------------
#define SM_AHI 0
#define SM_ALO 16384
#define SM_BHI 32768
#define SM_BLO 40960
#define SM_TOTAL 49152

__global__ __launch_bounds__(256) void mma_proj_kernel(
    const float* __restrict__ bq, const float* __restrict__ bk,
    const float* __restrict__ bv, const float* __restrict__ bo,
    float* __restrict__ out, int is_oproj)
{
    extern __shared__ char smem[];
    uint32_t sb = smem_u32(smem);
    const int tid  = threadIdx.x;
    const int wid  = tid >> 5, lane = tid & 31;
    const int wr   = wid >> 1, wc = wid & 1;
    const int z    = blockIdx.z;
    const int n0b  = blockIdx.y * 128;
    const int o0   = blockIdx.x * 64;

    const __nv_bfloat16 *xh, *xl, *wh, *wl;
    const float* bias;
    if (is_oproj) {
        xh = g_ahi; xl = g_alo;
        wh = g_whi + 3*WOFF; wl = g_wlo + 3*WOFF;
        bias = bo;
    } else {
        xh = g_xhi + (size_t)z*XOFF; xl = g_xlo + (size_t)z*XOFF;
        wh = g_whi + (size_t)z*WOFF; wl = g_wlo + (size_t)z*WOFF;
        bias = (z == 0) ? bq : (z == 1) ? bk : bv;
    }

    const __nv_bfloat16* xhp = xh + (size_t)n0b * D_MODEL;
    const __nv_bfloat16* xlp = xl + (size_t)n0b * D_MODEL;
    const __nv_bfloat16* whp = wh + (size_t)o0  * D_MODEL;
    const __nv_bfloat16* wlp = wl + (size_t)o0  * D_MODEL;

    float acc[2][4][4];
#pragma unroll
    for (int mt = 0; mt < 2; mt++)
#pragma unroll
        for (int nt = 0; nt < 4; nt++)
#pragma unroll
            for (int r = 0; r < 4; r++) acc[mt][nt][r] = 0.f;

    // ldmatrix per-lane smem addresses (row-of-8x8 layout; see fragment maps)
    // A tile m16k16 at (row0, ks): lane l -> row row0+(l&15), kcol ks*16+(l>>4)*8
    // B x4 covering n-tiles {g*16, g*16+8} at ks: lane l (m=l>>3) ->
    //   row n0+(m>>1)*8+(l&7), kcol ks*16+(m&1)*8
    const int a_r = lane & 15, a_k8 = (lane >> 4) * 8;
    const int b_m = lane >> 3;
    const int b_r = (b_m >> 1) * 8 + (lane & 7), b_k8 = (b_m & 1) * 8;

#pragma unroll 1
    for (int kc = 0; kc < D_MODEL; kc += 64) {
        // stage A hi/lo: 128 rows x 128B
#pragma unroll
        for (int r = 0; r < 4; r++) {
            int idx = tid + r*256;
            int row = idx >> 3, seg = idx & 7;
            uint32_t so = SWZ128(row*128 + seg*16);
            *(uint4*)(smem + SM_AHI + so) = *(const uint4*)(xhp + (size_t)row*D_MODEL + kc + seg*8);
            *(uint4*)(smem + SM_ALO + so) = *(const uint4*)(xlp + (size_t)row*D_MODEL + kc + seg*8);
        }
        // stage B hi/lo: 64 rows x 128B
#pragma unroll
        for (int r = 0; r < 2; r++) {
            int idx = tid + r*256;
            int row = idx >> 3, seg = idx & 7;
            uint32_t so = SWZ128(row*128 + seg*16);
            *(uint4*)(smem + SM_BHI + so) = *(const uint4*)(whp + (size_t)row*D_MODEL + kc + seg*8);
            *(uint4*)(smem + SM_BLO + so) = *(const uint4*)(wlp + (size_t)row*D_MODEL + kc + seg*8);
        }
        __syncthreads();

#pragma unroll
        for (int ks = 0; ks < 4; ks++) {
            const int kcol = ks*16 + a_k8;
            uint32_t ah[2][4], al[2][4];
#pragma unroll
            for (int mt = 0; mt < 2; mt++) {
                int row = wr*32 + mt*16 + a_r;
                uint32_t off = SWZ128(row*128 + kcol*2);
                LDSM4(ah[mt], sb + SM_AHI + off);
                LDSM4(al[mt], sb + SM_ALO + off);
            }
            uint32_t bh[2][4], bl[2][4];
#pragma unroll
            for (int g = 0; g < 2; g++) {
                int row = wc*32 + g*16 + b_r;
                uint32_t off = SWZ128(row*128 + (ks*16 + b_k8)*2);
                LDSM4(bh[g], sb + SM_BHI + off);
                LDSM4(bl[g], sb + SM_BLO + off);
            }
#pragma unroll
            for (int mt = 0; mt < 2; mt++)
#pragma unroll
                for (int nt = 0; nt < 4; nt++) {
                    uint32_t b0h = bh[nt>>1][(nt&1)*2], b1h = bh[nt>>1][(nt&1)*2+1];
                    uint32_t b0l = bl[nt>>1][(nt&1)*2], b1l = bl[nt>>1][(nt&1)*2+1];
                    MMA16816(acc[mt][nt], ah[mt], b0h, b1h);
                    MMA16816(acc[mt][nt], ah[mt], b0l, b1l);
                    MMA16816(acc[mt][nt], al[mt], b0h, b1h);
                }
        }
        __syncthreads();
    }

    // epilogue: C frag (m16n8): c0,c1 @ (row0+lane/4, n0+(lane%4)*2 {+1});
    //           c2,c3 @ row+8
    const int cr = lane >> 2, cc = (lane & 3) * 2;
#pragma unroll
    for (int mt = 0; mt < 2; mt++) {
#pragma unroll
        for (int nt = 0; nt < 4; nt++) {
            int colh = wc*32 + nt*8 + cc;         // col within 64-wide tile
            float b0 = bias[o0 + colh], b1 = bias[o0 + colh + 1];
#pragma unroll
            for (int half = 0; half < 2; half++) {
                int rloc = wr*32 + mt*16 + cr + half*8;
                int n = n0b + rloc;
                float v0 = acc[mt][nt][half*2+0] + b0;
                float v1 = acc[mt][nt][half*2+1] + b1;
                if (is_oproj) {
                    float2* dp = (float2*)(out + (size_t)n * D_MODEL + o0 + colh);
                    *dp = make_float2(v0, v1);
                } else {
                    float* dst = (z == 0) ? g_q : (z == 1) ? g_k : g_v;
                    int b = n >> 11, s = n & (SEQ - 1);
                    float2* dp = (float2*)(dst +
                        (((size_t)(b*NUM_HEADS + blockIdx.x))*SEQ + s)*DQK + colh);
                    *dp = make_float2(v0, v1);
                }
            }
        }
    }
}

// ---------------------------------------------------------------------------
// Flash-style causal attention per (b, h, 64-row q tile). 256 threads.
// Unchanged from R11 passing kernel (prefetch + heavy-first block order).
// ---------------------------------------------------------------------------
#define QK_LDT 68
#define P_LDS  65
#define ATTN_SMEM_BYTES ((64*QK_LDT + 64*64 + 64*QK_LDT) * 4)

__global__ __launch_bounds__(256) void attn_kernel(float* __restrict__ scores)
{
    extern __shared__ float sm[];
    float* QsT = sm;                       // [dd][row]  stride 68
    float* Vs  = sm + 64*QK_LDT;           // [kk][col]  stride 64
    float* KT  = Vs + 64*64;               // [dd][krow] stride 68; reused as P
    float* Ps  = KT;                       // [qrow][kk] stride 65

    const int tid = threadIdx.x;
    const int tx  = tid & 15;
    const int ty  = tid >> 4;
    const int t   = (SEQ/64 - 1) - blockIdx.x;   // heavy tiles launch first
    const int h   = blockIdx.y;
    const int b   = blockIdx.z;
    const int bh  = b * NUM_HEADS + h;

    const float* qbase = g_q + (size_t)bh * SEQ * DQK;
    const float* kbase = g_k + (size_t)bh * SEQ * DQK;
    const float* vbase = g_v + (size_t)bh * SEQ * DQK;
    float* sc = scores + (size_t)bh * SEQ * SEQ;
    const int r0 = t * 64;

    const int lrow = tid >> 2;             // 0..63
    const int dg   = (tid & 3) * 4;        // 0,4,8,12

#pragma unroll
    for (int c = 0; c < 4; c++) {
        int col = dg + c*16;
        float4 qv = *(const float4*)(qbase + (size_t)(r0 + lrow)*DQK + col);
        QsT[(col+0)*QK_LDT + lrow] = qv.x; QsT[(col+1)*QK_LDT + lrow] = qv.y;
        QsT[(col+2)*QK_LDT + lrow] = qv.z; QsT[(col+3)*QK_LDT + lrow] = qv.w;
    }

    float m_i[4], l_i[4];
    u64 O2[4][2];
#pragma unroll
    for (int i = 0; i < 4; i++) {
        m_i[i] = -1e30f; l_i[i] = 0.f;
        O2[i][0] = 0ull; O2[i][1] = 0ull;
    }

    float4 kpre[4], vpre[4];
#pragma unroll
    for (int c = 0; c < 4; c++) {
        int col = dg + c*16;
        kpre[c] = *(const float4*)(kbase + (size_t)lrow*DQK + col);
        vpre[c] = *(const float4*)(vbase + (size_t)lrow*DQK + col);
    }

    for (int jt = 0; jt <= t; jt++) {
#pragma unroll
        for (int c = 0; c < 4; c++) {
            int col = dg + c*16;
            KT[(col+0)*QK_LDT + lrow] = kpre[c].x; KT[(col+1)*QK_LDT + lrow] = kpre[c].y;
            KT[(col+2)*QK_LDT + lrow] = kpre[c].z; KT[(col+3)*QK_LDT + lrow] = kpre[c].w;
            *(float4*)&Vs[lrow*64 + col] = vpre[c];
        }
        __syncthreads();

        if (jt < t) {
#pragma unroll
            for (int c = 0; c < 4; c++) {
                int col = dg + c*16;
                kpre[c] = *(const float4*)(kbase + (size_t)((jt+1)*64 + lrow)*DQK + col);
                vpre[c] = *(const float4*)(vbase + (size_t)((jt+1)*64 + lrow)*DQK + col);
            }
        }

        u64 s2[4][2];
#pragma unroll
        for (int i = 0; i < 4; i++) { s2[i][0] = 0ull; s2[i][1] = 0ull; }

#pragma unroll 4
        for (int dd = 0; dd < DQK; dd++) {
            float4 a = *(const float4*)&QsT[dd*QK_LDT + ty*4];
            float4 bq4 = *(const float4*)&KT[dd*QK_LDT + tx*4];
            u64 b0 = pk2(bq4.x, bq4.y);
            u64 b1 = pk2(bq4.z, bq4.w);
            float av[4] = {a.x, a.y, a.z, a.w};
#pragma unroll
            for (int i = 0; i < 4; i++) {
                u64 ad = pk2(av[i], av[i]);
                ffma2(s2[i][0], ad, b0);
                ffma2(s2[i][1], ad, b1);
            }
        }

        float s4[4][4];
#pragma unroll
        for (int i = 0; i < 4; i++) {
            upk2(s2[i][0], s4[i][0], s4[i][1]);
            upk2(s2[i][1], s4[i][2], s4[i][3]);
            int qrow = r0 + ty*4 + i;
#pragma unroll
            for (int j = 0; j < 4; j++) {
                int kcol = jt*64 + tx*4 + j;
                float v = s4[i][j] * 0.125f;
                v = (kcol <= qrow) ? v : NEG_INF_F;
                s4[i][j] = v;
            }
            *(float4*)&sc[(size_t)qrow*SEQ + jt*64 + tx*4] =
                make_float4(s4[i][0], s4[i][1], s4[i][2], s4[i][3]);
        }
        __syncthreads();

#pragma unroll
        for (int i = 0; i < 4; i++) {
            float tm = fmaxf(fmaxf(s4[i][0], s4[i][1]), fmaxf(s4[i][2], s4[i][3]));
            tm = fmaxf(tm, __shfl_xor_sync(0xffffffffu, tm, 8));
            tm = fmaxf(tm, __shfl_xor_sync(0xffffffffu, tm, 4));
            tm = fmaxf(tm, __shfl_xor_sync(0xffffffffu, tm, 2));
            tm = fmaxf(tm, __shfl_xor_sync(0xffffffffu, tm, 1));
            float mnew = fmaxf(m_i[i], tm);
            float corr = __expf(m_i[i] - mnew);
            float rs = 0.f;
#pragma unroll
            for (int j = 0; j < 4; j++) {
                float p = __expf(s4[i][j] - mnew);
                s4[i][j] = p;
                rs += p;
            }
            rs += __shfl_xor_sync(0xffffffffu, rs, 8);
            rs += __shfl_xor_sync(0xffffffffu, rs, 4);
            rs += __shfl_xor_sync(0xffffffffu, rs, 2);
            rs += __shfl_xor_sync(0xffffffffu, rs, 1);
            l_i[i] = l_i[i] * corr + rs;
            m_i[i] = mnew;
            u64 cd = pk2(corr, corr);
            O2[i][0] = fmul2(O2[i][0], cd);
            O2[i][1] = fmul2(O2[i][1], cd);
#pragma unroll
            for (int j = 0; j < 4; j++)
                Ps[(ty*4+i)*P_LDS + tx*4 + j] = s4[i][j];
        }
        __syncthreads();

#pragma unroll 4
        for (int kk = 0; kk < 64; kk++) {
            float4 vvv = *(const float4*)&Vs[kk*64 + tx*4];
            u64 v0 = pk2(vvv.x, vvv.y);
            u64 v1 = pk2(vvv.z, vvv.w);
#pragma unroll
            for (int i = 0; i < 4; i++) {
                float a = Ps[(ty*4+i)*P_LDS + kk];
                u64 ad = pk2(a, a);
                ffma2(O2[i][0], ad, v0);
                ffma2(O2[i][1], ad, v1);
            }
        }
        __syncthreads();
    }

#pragma unroll
    for (int i = 0; i < 4; i++) {
        float inv = 1.0f / l_i[i];
        int row = r0 + ty*4 + i;
        float o[4];
        upk2(O2[i][0], o[0], o[1]);
        upk2(O2[i][1], o[2], o[3]);
        *(float4*)&g_attn[((size_t)(b*SEQ + row))*D_MODEL + h*DQK + tx*4] =
            make_float4(o[0]*inv, o[1]*inv, o[2]*inv, o[3]*inv);
    }

    int rem = 31 - t;
    if (rem > 0) {
        int wf4 = rem * 16;
        int total = 64 * wf4;
        float4 nv = make_float4(NEG_INF_F, NEG_INF_F, NEG_INF_F, NEG_INF_F);
        for (int idx = tid; idx < total; idx += 256) {
            int rr = idx / wf4;
            int cc = idx - rr * wf4;
            *(float4*)&sc[(size_t)(r0 + rr)*SEQ + (t+1)*64 + cc*4] = nv;
        }
    }
}

extern "C" void kernel_launch(void* const* d_in, const int* in_sizes, int n_in,
                              void* d_out, int out_size)
{
    const float* Q  = (const float*)d_in[0];
    const float* K  = (const float*)d_in[1];
    const float* V  = (const float*)d_in[2];
    // d_in[3] = mask (bool causal) — deterministic, not needed
    const float* Wq = (const float*)d_in[4];
    const float* bq = (const float*)d_in[5];
    const float* Wk = (const float*)d_in[6];
    const float* bk = (const float*)d_in[7];
    const float* Wv = (const float*)d_in[8];
    const float* bv = (const float*)d_in[9];
    const float* Wo = (const float*)d_in[10];
    const float* bo = (const float*)d_in[11];

    float* out    = (float*)d_out;                       // [B,S,768]
    float* scores = out + (size_t)NROWS * D_MODEL;       // [B,H,S,S]

    cudaFuncSetAttribute(attn_kernel,
                         cudaFuncAttributeMaxDynamicSharedMemorySize,
                         ATTN_SMEM_BYTES);
    cudaFuncSetAttribute(mma_proj_kernel,
                         cudaFuncAttributeMaxDynamicSharedMemorySize,
                         SM_TOTAL);

    const int nx = NROWS * D_MODEL;      // 3145728
    const int nw = D_MODEL * D_MODEL;    // 589824

    convert_kernel<<<nx/512, 256>>>(Q,  nx, 0);
    convert_kernel<<<nx/512, 256>>>(K,  nx, 1);
    convert_kernel<<<nx/512, 256>>>(V,  nx, 2);
    convert_kernel<<<nw/512, 256>>>(Wq, nw, 3);
    convert_kernel<<<nw/512, 256>>>(Wk, nw, 4);
    convert_kernel<<<nw/512, 256>>>(Wv, nw, 5);
    convert_kernel<<<nw/512, 256>>>(Wo, nw, 6);

    mma_proj_kernel<<<dim3(12, 32, 3), 256, SM_TOTAL>>>(bq, bk, bv, bo, nullptr, 0);

    dim3 agrid(SEQ / 64, NUM_HEADS, BATCH);      // (32, 12, 2)
    attn_kernel<<<agrid, 256, ATTN_SMEM_BYTES>>>(scores);

    convert_kernel<<<nx/512, 256>>>(nullptr, nx, 7);

    mma_proj_kernel<<<dim3(12, 32, 1), 256, SM_TOTAL>>>(bq, bk, bv, bo, out, 1);
}